// round 4
// baseline (speedup 1.0000x reference)
#include <cuda_runtime.h>

#define N_NODES  50000
#define IN_DIM   128
#define HID      64
#define OUT_DIM  128
#define N_GRAPHS 128
#define NH       (N_NODES * HID)   // 3,200,000 floats

// One big scratch: h0 | h1 | agg0 | agg1 | pool_sum | pool_cnt
__device__ float g_scratch[4 * NH + N_GRAPHS * OUT_DIM + N_GRAPHS];

__device__ __forceinline__ void fma4(float4& a, float s, float4 w) {
    a.x = fmaf(s, w.x, a.x);
    a.y = fmaf(s, w.y, a.y);
    a.z = fmaf(s, w.z, a.z);
    a.w = fmaf(s, w.w, a.w);
}

__device__ __forceinline__ float4 relu4(float4 v) {
    v.x = fmaxf(v.x, 0.f); v.y = fmaxf(v.y, 0.f);
    v.z = fmaxf(v.z, 0.f); v.w = fmaxf(v.w, 0.f);
    return v;
}

// ---------------------------------------------------------------------------
// Zero the accumulator regions (agg0, agg1, pool, cnt) — they are contiguous.
// ---------------------------------------------------------------------------
__global__ void zero_kernel(float* __restrict__ p, int n4) {
    const float4 z = make_float4(0.f, 0.f, 0.f, 0.f);
    int i = blockIdx.x * blockDim.x + threadIdx.x;
    int stride = gridDim.x * blockDim.x;
    for (int j = i; j < n4; j += stride)
        ((float4*)p)[j] = z;
}

// ---------------------------------------------------------------------------
// proj_in: out[n, 0:64] = x[n, 0:128] @ W[128,64] + b
// Block 256 threads: 16 col-groups (4 cols each) x 16 slots (4 nodes each)
// = 64 nodes per block iteration. W + 64 x-rows staged in 64KB dynamic smem.
// ---------------------------------------------------------------------------
__global__ void proj_in_kernel(const float* __restrict__ x,
                               const float* __restrict__ W,
                               const float* __restrict__ b,
                               float* __restrict__ out) {
    extern __shared__ float sh[];
    float* wsh = sh;                 // 128*64 = 8192 floats
    float* xsh = sh + IN_DIM * HID;  // 64*128 = 8192 floats
    const int tid = threadIdx.x;

    for (int i = tid; i < IN_DIM * HID / 4; i += 256)
        ((float4*)wsh)[i] = ((const float4*)W)[i];

    const int cg   = tid & 15;   // column group: cols [cg*4, cg*4+4)
    const int slot = tid >> 4;   // 16 slots, 4 nodes each
    const float4 b4 = ((const float4*)b)[cg];

    for (int base = blockIdx.x * 64; base < N_NODES; base += gridDim.x * 64) {
        __syncthreads();
        // stage 64 x rows (also guards first-iteration W load)
        for (int i = tid; i < 64 * IN_DIM / 4; i += 256) {
            int node = base + (i >> 5);            // 32 float4 per row
            float4 v = make_float4(0.f, 0.f, 0.f, 0.f);
            if (node < N_NODES)
                v = ((const float4*)x)[node * (IN_DIM / 4) + (i & 31)];
            ((float4*)xsh)[i] = v;
        }
        __syncthreads();

        float4 a0 = b4, a1 = b4, a2 = b4, a3 = b4;
        const float* t0 = xsh + (slot * 4 + 0) * IN_DIM;
        const float* t1 = t0 + IN_DIM;
        const float* t2 = t1 + IN_DIM;
        const float* t3 = t2 + IN_DIM;
#pragma unroll 8
        for (int k = 0; k < IN_DIM; k++) {
            float4 w4 = ((float4*)wsh)[k * 16 + cg];
            fma4(a0, t0[k], w4);
            fma4(a1, t1[k], w4);
            fma4(a2, t2[k], w4);
            fma4(a3, t3[k], w4);
        }
        int node = base + slot * 4;
        if (node + 0 < N_NODES) ((float4*)(out + (node + 0) * HID))[cg] = a0;
        if (node + 1 < N_NODES) ((float4*)(out + (node + 1) * HID))[cg] = a1;
        if (node + 2 < N_NODES) ((float4*)(out + (node + 2) * HID))[cg] = a2;
        if (node + 3 < N_NODES) ((float4*)(out + (node + 3) * HID))[cg] = a3;
    }
}

// ---------------------------------------------------------------------------
// Edge scatter-add: one warp per edge. Each lane moves 8 bytes (float2) of
// the 256B row, gather from h[src], vectorized reduction into agg[dst].
// ---------------------------------------------------------------------------
__global__ void scatter_kernel(const int* __restrict__ ei,
                               const float* __restrict__ h,
                               float* __restrict__ agg, int n_edges) {
    int w    = (blockIdx.x * blockDim.x + threadIdx.x) >> 5;
    int lane = threadIdx.x & 31;
    if (w >= n_edges) return;
    int src = ei[w];
    int dst = ei[n_edges + w];
    float2 v = ((const float2*)(h + (long)src * HID))[lane];
    float* addr = agg + (long)dst * HID + lane * 2;
    asm volatile("red.global.add.v2.f32 [%0], {%1, %2};"
                 :: "l"(addr), "f"(v.x), "f"(v.y) : "memory");
}

// ---------------------------------------------------------------------------
// GIN MLP (one conv): t = hin + agg; z = relu(t@W1+b1); out = relu(z@W2+b2)
// (outer relu is the conv-level relu in the reference).
// Block 256: 16 col-groups x 16 slots x 4 nodes = 64 nodes/iter.
// Static shared: W1 (16KB) + W2 (16KB) + t-buffer (16KB) = 48KB.
// The t-buffer is reused for z between GEMVs.
// ---------------------------------------------------------------------------
__global__ void gin_mlp_kernel(const float* __restrict__ hin,
                               const float* __restrict__ agg,
                               const float* __restrict__ W1,
                               const float* __restrict__ b1,
                               const float* __restrict__ W2,
                               const float* __restrict__ b2,
                               float* __restrict__ hout) {
    __shared__ float w1sh[HID * HID];
    __shared__ float w2sh[HID * HID];
    __shared__ float tsh[64 * HID];
    const int tid = threadIdx.x;

    for (int i = tid; i < HID * HID / 4; i += 256) {
        ((float4*)w1sh)[i] = ((const float4*)W1)[i];
        ((float4*)w2sh)[i] = ((const float4*)W2)[i];
    }

    const int cg   = tid & 15;
    const int slot = tid >> 4;
    const float4 b14 = ((const float4*)b1)[cg];
    const float4 b24 = ((const float4*)b2)[cg];

    for (int base = blockIdx.x * 64; base < N_NODES; base += gridDim.x * 64) {
        __syncthreads();
        // stage t = hin + agg for 64 nodes (64*64 floats = 1024 float4)
        for (int i = tid; i < 1024; i += 256) {
            int node = base + (i >> 4);
            float4 v = make_float4(0.f, 0.f, 0.f, 0.f);
            if (node < N_NODES) {
                float4 a = ((const float4*)hin)[node * (HID / 4) + (i & 15)];
                float4 g = ((const float4*)agg)[node * (HID / 4) + (i & 15)];
                v.x = a.x + g.x; v.y = a.y + g.y;
                v.z = a.z + g.z; v.w = a.w + g.w;
            }
            ((float4*)tsh)[i] = v;
        }
        __syncthreads();

        const float* t0 = tsh + (slot * 4 + 0) * HID;
        const float* t1 = t0 + HID;
        const float* t2 = t1 + HID;
        const float* t3 = t2 + HID;

        // GEMV 1
        float4 z0 = b14, z1 = b14, z2 = b14, z3 = b14;
#pragma unroll 16
        for (int k = 0; k < HID; k++) {
            float4 w4 = ((float4*)w1sh)[k * 16 + cg];
            fma4(z0, t0[k], w4);
            fma4(z1, t1[k], w4);
            fma4(z2, t2[k], w4);
            fma4(z3, t3[k], w4);
        }
        z0 = relu4(z0); z1 = relu4(z1); z2 = relu4(z2); z3 = relu4(z3);

        __syncthreads();  // all reads of tsh complete
        ((float4*)tsh)[(slot * 4 + 0) * 16 + cg] = z0;
        ((float4*)tsh)[(slot * 4 + 1) * 16 + cg] = z1;
        ((float4*)tsh)[(slot * 4 + 2) * 16 + cg] = z2;
        ((float4*)tsh)[(slot * 4 + 3) * 16 + cg] = z3;
        __syncthreads();

        // GEMV 2
        float4 o0 = b24, o1 = b24, o2 = b24, o3 = b24;
#pragma unroll 16
        for (int k = 0; k < HID; k++) {
            float4 w4 = ((float4*)w2sh)[k * 16 + cg];
            fma4(o0, t0[k], w4);
            fma4(o1, t1[k], w4);
            fma4(o2, t2[k], w4);
            fma4(o3, t3[k], w4);
        }
        o0 = relu4(o0); o1 = relu4(o1); o2 = relu4(o2); o3 = relu4(o3);

        int node = base + slot * 4;
        if (node + 0 < N_NODES) ((float4*)(hout + (node + 0) * HID))[cg] = o0;
        if (node + 1 < N_NODES) ((float4*)(hout + (node + 1) * HID))[cg] = o1;
        if (node + 2 < N_NODES) ((float4*)(hout + (node + 2) * HID))[cg] = o2;
        if (node + 3 < N_NODES) ((float4*)(hout + (node + 3) * HID))[cg] = o3;
    }
}

// ---------------------------------------------------------------------------
// proj_out + global mean pool accumulation.
// o[n, 0:128] = h[n, 0:64] @ W_out + b_out, then red.v4 into pool[batch[n]].
// Block 256: 32 col-groups (4 cols) x 8 slots x 4 nodes = 32 nodes/iter.
// ---------------------------------------------------------------------------
__global__ void proj_out_pool_kernel(const float* __restrict__ h,
                                     const int* __restrict__ batch,
                                     const float* __restrict__ W,
                                     const float* __restrict__ b,
                                     float* __restrict__ pool,
                                     float* __restrict__ cnt) {
    __shared__ float wsh[HID * OUT_DIM];  // 8192 floats, 32KB
    __shared__ float hsh[32 * HID];       // 2048 floats, 8KB
    const int tid = threadIdx.x;

    for (int i = tid; i < HID * OUT_DIM / 4; i += 256)
        ((float4*)wsh)[i] = ((const float4*)W)[i];

    const int cg   = tid & 31;
    const int slot = tid >> 5;
    const float4 b4 = ((const float4*)b)[cg];

    for (int base = blockIdx.x * 32; base < N_NODES; base += gridDim.x * 32) {
        __syncthreads();
        for (int i = tid; i < 32 * HID / 4; i += 256) {
            int node = base + (i >> 4);
            float4 v = make_float4(0.f, 0.f, 0.f, 0.f);
            if (node < N_NODES)
                v = ((const float4*)h)[node * (HID / 4) + (i & 15)];
            ((float4*)hsh)[i] = v;
        }
        __syncthreads();

        float4 a0 = b4, a1 = b4, a2 = b4, a3 = b4;
        const float* t0 = hsh + (slot * 4 + 0) * HID;
        const float* t1 = t0 + HID;
        const float* t2 = t1 + HID;
        const float* t3 = t2 + HID;
#pragma unroll 16
        for (int k = 0; k < HID; k++) {
            float4 w4 = ((float4*)wsh)[k * 32 + cg];
            fma4(a0, t0[k], w4);
            fma4(a1, t1[k], w4);
            fma4(a2, t2[k], w4);
            fma4(a3, t3[k], w4);
        }

        int node = base + slot * 4;
#pragma unroll
        for (int j = 0; j < 4; j++) {
            int n = node + j;
            if (n < N_NODES) {
                float4 a = (j == 0) ? a0 : (j == 1) ? a1 : (j == 2) ? a2 : a3;
                int g = batch[n];
                float* addr = pool + g * OUT_DIM + cg * 4;
                asm volatile("red.global.add.v4.f32 [%0], {%1, %2, %3, %4};"
                             :: "l"(addr), "f"(a.x), "f"(a.y), "f"(a.z), "f"(a.w)
                             : "memory");
                if (cg == 0)
                    atomicAdd(cnt + g, 1.0f);
            }
        }
    }
}

// ---------------------------------------------------------------------------
__global__ void finalize_kernel(const float* __restrict__ pool,
                                const float* __restrict__ cnt,
                                float* __restrict__ out) {
    int i = blockIdx.x * blockDim.x + threadIdx.x;
    if (i < N_GRAPHS * OUT_DIM)
        out[i] = pool[i] / fmaxf(cnt[i >> 7], 1.0f);
}

// ---------------------------------------------------------------------------
extern "C" void kernel_launch(void* const* d_in, const int* in_sizes, int n_in,
                              void* d_out, int out_size) {
    const float* x     = (const float*)d_in[0];
    const int*   ei    = (const int*)d_in[1];   // [2, E] int32
    const int*   batch = (const int*)d_in[2];   // [N] int32
    const float* W_in  = (const float*)d_in[3];
    const float* b_in  = (const float*)d_in[4];
    const float* W1_0  = (const float*)d_in[5];
    const float* b1_0  = (const float*)d_in[6];
    const float* W2_0  = (const float*)d_in[7];
    const float* b2_0  = (const float*)d_in[8];
    const float* W1_1  = (const float*)d_in[9];
    const float* b1_1  = (const float*)d_in[10];
    const float* W2_1  = (const float*)d_in[11];
    const float* b2_1  = (const float*)d_in[12];
    const float* W_out = (const float*)d_in[13];
    const float* b_out = (const float*)d_in[14];
    const int n_edges  = in_sizes[1] / 2;
    float* out = (float*)d_out;

    void* basep = nullptr;
    cudaGetSymbolAddress(&basep, g_scratch);
    float* h0   = (float*)basep;
    float* h1   = h0 + NH;
    float* a0   = h1 + NH;
    float* a1   = a0 + NH;
    float* pool = a1 + NH;
    float* cnt  = pool + N_GRAPHS * OUT_DIM;

    // zero agg0 | agg1 | pool | cnt (contiguous)
    const int zero_n4 = (2 * NH + N_GRAPHS * OUT_DIM + N_GRAPHS) / 4;
    zero_kernel<<<512, 256>>>(a0, zero_n4);

    cudaFuncSetAttribute(proj_in_kernel,
                         cudaFuncAttributeMaxDynamicSharedMemorySize, 65536);
    const int g64 = (N_NODES + 63) / 64;
    const int g32 = (N_NODES + 31) / 32;
    const int ge  = (n_edges * 32 + 255) / 256;

    proj_in_kernel<<<g64, 256, 65536>>>(x, W_in, b_in, h0);
    scatter_kernel<<<ge, 256>>>(ei, h0, a0, n_edges);
    gin_mlp_kernel<<<g64, 256>>>(h0, a0, W1_0, b1_0, W2_0, b2_0, h1);
    scatter_kernel<<<ge, 256>>>(ei, h1, a1, n_edges);
    gin_mlp_kernel<<<g64, 256>>>(h1, a1, W1_1, b1_1, W2_1, b2_1, h0);
    proj_out_pool_kernel<<<g32, 256>>>(h0, batch, W_out, b_out, pool, cnt);
    finalize_kernel<<<(N_GRAPHS * OUT_DIM + 255) / 256, 256>>>(pool, cnt, out);
}

// round 5
// speedup vs baseline: 1.2213x; 1.2213x over previous
#include <cuda_runtime.h>

#define N_NODES  50000
#define IN_DIM   128
#define HID      64
#define OUT_DIM  128
#define N_GRAPHS 128
#define NH       (N_NODES * HID)   // 3,200,000 floats

// One big scratch: h0 | h1 | agg0 | agg1 | pool_sum | pool_cnt
__device__ float g_scratch[4 * NH + N_GRAPHS * OUT_DIM + N_GRAPHS];

using u64 = unsigned long long;

// ---- packed f32x2 helpers (Blackwell FFMA2 — PTX-only) --------------------
__device__ __forceinline__ u64 pack2(float x, float y) {
    u64 r; asm("mov.b64 %0, {%1, %2};" : "=l"(r) : "f"(x), "f"(y)); return r;
}
__device__ __forceinline__ u64 pack2s(float s) {
    u64 r; asm("mov.b64 %0, {%1, %1};" : "=l"(r) : "f"(s)); return r;
}
__device__ __forceinline__ void ffma2(u64& a, u64 s, u64 w) {
    asm("fma.rn.f32x2 %0, %1, %2, %3;" : "=l"(a) : "l"(s), "l"(w), "l"(a));
}
__device__ __forceinline__ float2 unpack2(u64 v) {
    float2 f; asm("mov.b64 {%0, %1}, %2;" : "=f"(f.x), "=f"(f.y) : "l"(v));
    return f;
}

struct Acc4 { u64 lo, hi; };

__device__ __forceinline__ Acc4 acc_init(float4 b) {
    Acc4 a; a.lo = pack2(b.x, b.y); a.hi = pack2(b.z, b.w); return a;
}
__device__ __forceinline__ void fma2x2(Acc4& a, u64 s2, ulonglong2 w) {
    ffma2(a.lo, s2, w.x);
    ffma2(a.hi, s2, w.y);
}
__device__ __forceinline__ float4 acc_to_f4(Acc4 a) {
    float2 l = unpack2(a.lo), h = unpack2(a.hi);
    return make_float4(l.x, l.y, h.x, h.y);
}
__device__ __forceinline__ float4 relu4(float4 v) {
    v.x = fmaxf(v.x, 0.f); v.y = fmaxf(v.y, 0.f);
    v.z = fmaxf(v.z, 0.f); v.w = fmaxf(v.w, 0.f);
    return v;
}

// ---------------------------------------------------------------------------
// Zero the accumulator regions (agg0, agg1, pool, cnt) — contiguous.
// ---------------------------------------------------------------------------
__global__ void zero_kernel(float* __restrict__ p, int n4) {
    const float4 z = make_float4(0.f, 0.f, 0.f, 0.f);
    int i = blockIdx.x * blockDim.x + threadIdx.x;
    int stride = gridDim.x * blockDim.x;
    for (int j = i; j < n4; j += stride)
        ((float4*)p)[j] = z;
}

// ---------------------------------------------------------------------------
// proj_in: out[n, 0:64] = x[n, 0:128] @ W[128,64] + b
// 256 threads: 16 col-groups (4 cols) x 16 slots (4 nodes) = 64 nodes/iter.
// ---------------------------------------------------------------------------
__global__ void proj_in_kernel(const float* __restrict__ x,
                               const float* __restrict__ W,
                               const float* __restrict__ b,
                               float* __restrict__ out) {
    extern __shared__ float sh[];
    float* wsh = sh;                 // 128*64 = 8192 floats
    float* xsh = sh + IN_DIM * HID;  // 64*128 = 8192 floats
    const int tid = threadIdx.x;

    for (int i = tid; i < IN_DIM * HID / 4; i += 256)
        ((float4*)wsh)[i] = ((const float4*)W)[i];

    const int cg   = tid & 15;
    const int slot = tid >> 4;
    const float4 b4 = ((const float4*)b)[cg];

    for (int base = blockIdx.x * 64; base < N_NODES; base += gridDim.x * 64) {
        __syncthreads();
        for (int i = tid; i < 64 * IN_DIM / 4; i += 256) {
            int node = base + (i >> 5);
            float4 v = make_float4(0.f, 0.f, 0.f, 0.f);
            if (node < N_NODES)
                v = ((const float4*)x)[node * (IN_DIM / 4) + (i & 31)];
            ((float4*)xsh)[i] = v;
        }
        __syncthreads();

        Acc4 a0 = acc_init(b4), a1 = a0, a2 = a0, a3 = a0;
        const float4* t0 = (const float4*)(xsh + (slot * 4 + 0) * IN_DIM);
        const float4* t1 = (const float4*)(xsh + (slot * 4 + 1) * IN_DIM);
        const float4* t2 = (const float4*)(xsh + (slot * 4 + 2) * IN_DIM);
        const float4* t3 = (const float4*)(xsh + (slot * 4 + 3) * IN_DIM);
#pragma unroll 4
        for (int k4 = 0; k4 < IN_DIM / 4; k4++) {
            float4 s0 = t0[k4], s1 = t1[k4], s2 = t2[k4], s3 = t3[k4];
#pragma unroll
            for (int j = 0; j < 4; j++) {
                ulonglong2 w = ((const ulonglong2*)wsh)[(k4 * 4 + j) * 16 + cg];
                fma2x2(a0, pack2s(((const float*)&s0)[j]), w);
                fma2x2(a1, pack2s(((const float*)&s1)[j]), w);
                fma2x2(a2, pack2s(((const float*)&s2)[j]), w);
                fma2x2(a3, pack2s(((const float*)&s3)[j]), w);
            }
        }
        int node = base + slot * 4;
        if (node + 0 < N_NODES) ((float4*)(out + (node + 0) * HID))[cg] = acc_to_f4(a0);
        if (node + 1 < N_NODES) ((float4*)(out + (node + 1) * HID))[cg] = acc_to_f4(a1);
        if (node + 2 < N_NODES) ((float4*)(out + (node + 2) * HID))[cg] = acc_to_f4(a2);
        if (node + 3 < N_NODES) ((float4*)(out + (node + 3) * HID))[cg] = acc_to_f4(a3);
    }
}

// ---------------------------------------------------------------------------
// Edge scatter-add: 16 lanes per edge, 2 edges per warp.
// Each lane moves 16B (float4) of the 256B row via red.global.add.v4.f32.
// ---------------------------------------------------------------------------
__global__ void scatter_kernel(const int* __restrict__ ei,
                               const float* __restrict__ h,
                               float* __restrict__ agg, int n_edges) {
    int idx  = blockIdx.x * blockDim.x + threadIdx.x;
    int e    = idx >> 4;
    int lane = idx & 15;
    if (e >= n_edges) return;
    int src = __ldg(ei + e);
    int dst = __ldg(ei + n_edges + e);
    float4 v = ((const float4*)(h + (long)src * HID))[lane];
    float* addr = agg + (long)dst * HID + lane * 4;
    asm volatile("red.global.add.v4.f32 [%0], {%1, %2, %3, %4};"
                 :: "l"(addr), "f"(v.x), "f"(v.y), "f"(v.z), "f"(v.w)
                 : "memory");
}

// ---------------------------------------------------------------------------
// GIN MLP: t = hin + agg; z = relu(t@W1+b1); out = relu(z@W2+b2)
// 256 threads: 16 col-groups x 16 slots x 4 nodes = 64 nodes/iter.
// ---------------------------------------------------------------------------
__global__ void gin_mlp_kernel(const float* __restrict__ hin,
                               const float* __restrict__ agg,
                               const float* __restrict__ W1,
                               const float* __restrict__ b1,
                               const float* __restrict__ W2,
                               const float* __restrict__ b2,
                               float* __restrict__ hout) {
    __shared__ float w1sh[HID * HID];
    __shared__ float w2sh[HID * HID];
    __shared__ float tsh[64 * HID];
    const int tid = threadIdx.x;

    for (int i = tid; i < HID * HID / 4; i += 256) {
        ((float4*)w1sh)[i] = ((const float4*)W1)[i];
        ((float4*)w2sh)[i] = ((const float4*)W2)[i];
    }

    const int cg   = tid & 15;
    const int slot = tid >> 4;
    const float4 b14 = ((const float4*)b1)[cg];
    const float4 b24 = ((const float4*)b2)[cg];

    for (int base = blockIdx.x * 64; base < N_NODES; base += gridDim.x * 64) {
        __syncthreads();
        for (int i = tid; i < 1024; i += 256) {
            int node = base + (i >> 4);
            float4 v = make_float4(0.f, 0.f, 0.f, 0.f);
            if (node < N_NODES) {
                float4 a = ((const float4*)hin)[node * (HID / 4) + (i & 15)];
                float4 g = ((const float4*)agg)[node * (HID / 4) + (i & 15)];
                v.x = a.x + g.x; v.y = a.y + g.y;
                v.z = a.z + g.z; v.w = a.w + g.w;
            }
            ((float4*)tsh)[i] = v;
        }
        __syncthreads();

        const float4* t0 = (const float4*)(tsh + (slot * 4 + 0) * HID);
        const float4* t1 = (const float4*)(tsh + (slot * 4 + 1) * HID);
        const float4* t2 = (const float4*)(tsh + (slot * 4 + 2) * HID);
        const float4* t3 = (const float4*)(tsh + (slot * 4 + 3) * HID);

        // GEMV 1
        Acc4 z0 = acc_init(b14), z1 = z0, z2 = z0, z3 = z0;
#pragma unroll 4
        for (int k4 = 0; k4 < HID / 4; k4++) {
            float4 s0 = t0[k4], s1 = t1[k4], s2 = t2[k4], s3 = t3[k4];
#pragma unroll
            for (int j = 0; j < 4; j++) {
                ulonglong2 w = ((const ulonglong2*)w1sh)[(k4 * 4 + j) * 16 + cg];
                fma2x2(z0, pack2s(((const float*)&s0)[j]), w);
                fma2x2(z1, pack2s(((const float*)&s1)[j]), w);
                fma2x2(z2, pack2s(((const float*)&s2)[j]), w);
                fma2x2(z3, pack2s(((const float*)&s3)[j]), w);
            }
        }
        float4 zf0 = relu4(acc_to_f4(z0));
        float4 zf1 = relu4(acc_to_f4(z1));
        float4 zf2 = relu4(acc_to_f4(z2));
        float4 zf3 = relu4(acc_to_f4(z3));

        __syncthreads();  // all reads of tsh complete
        ((float4*)tsh)[(slot * 4 + 0) * 16 + cg] = zf0;
        ((float4*)tsh)[(slot * 4 + 1) * 16 + cg] = zf1;
        ((float4*)tsh)[(slot * 4 + 2) * 16 + cg] = zf2;
        ((float4*)tsh)[(slot * 4 + 3) * 16 + cg] = zf3;
        __syncthreads();

        // GEMV 2
        Acc4 o0 = acc_init(b24), o1 = o0, o2 = o0, o3 = o0;
#pragma unroll 4
        for (int k4 = 0; k4 < HID / 4; k4++) {
            float4 s0 = t0[k4], s1 = t1[k4], s2 = t2[k4], s3 = t3[k4];
#pragma unroll
            for (int j = 0; j < 4; j++) {
                ulonglong2 w = ((const ulonglong2*)w2sh)[(k4 * 4 + j) * 16 + cg];
                fma2x2(o0, pack2s(((const float*)&s0)[j]), w);
                fma2x2(o1, pack2s(((const float*)&s1)[j]), w);
                fma2x2(o2, pack2s(((const float*)&s2)[j]), w);
                fma2x2(o3, pack2s(((const float*)&s3)[j]), w);
            }
        }
        int node = base + slot * 4;
        if (node + 0 < N_NODES) ((float4*)(hout + (node + 0) * HID))[cg] = relu4(acc_to_f4(o0));
        if (node + 1 < N_NODES) ((float4*)(hout + (node + 1) * HID))[cg] = relu4(acc_to_f4(o1));
        if (node + 2 < N_NODES) ((float4*)(hout + (node + 2) * HID))[cg] = relu4(acc_to_f4(o2));
        if (node + 3 < N_NODES) ((float4*)(hout + (node + 3) * HID))[cg] = relu4(acc_to_f4(o3));
    }
}

// ---------------------------------------------------------------------------
// proj_out + global mean pool accumulation.
// 256 threads: 32 col-groups (4 cols) x 8 slots x 4 nodes = 32 nodes/iter.
// ---------------------------------------------------------------------------
__global__ void proj_out_pool_kernel(const float* __restrict__ h,
                                     const int* __restrict__ batch,
                                     const float* __restrict__ W,
                                     const float* __restrict__ b,
                                     float* __restrict__ pool,
                                     float* __restrict__ cnt) {
    __shared__ float wsh[HID * OUT_DIM];  // 32KB
    __shared__ float hsh[32 * HID];       // 8KB
    const int tid = threadIdx.x;

    for (int i = tid; i < HID * OUT_DIM / 4; i += 256)
        ((float4*)wsh)[i] = ((const float4*)W)[i];

    const int cg   = tid & 31;
    const int slot = tid >> 5;
    const float4 b4 = ((const float4*)b)[cg];

    for (int base = blockIdx.x * 32; base < N_NODES; base += gridDim.x * 32) {
        __syncthreads();
        for (int i = tid; i < 32 * HID / 4; i += 256) {
            int node = base + (i >> 4);
            float4 v = make_float4(0.f, 0.f, 0.f, 0.f);
            if (node < N_NODES)
                v = ((const float4*)h)[node * (HID / 4) + (i & 15)];
            ((float4*)hsh)[i] = v;
        }
        __syncthreads();

        Acc4 a0 = acc_init(b4), a1 = a0, a2 = a0, a3 = a0;
        const float4* t0 = (const float4*)(hsh + (slot * 4 + 0) * HID);
        const float4* t1 = (const float4*)(hsh + (slot * 4 + 1) * HID);
        const float4* t2 = (const float4*)(hsh + (slot * 4 + 2) * HID);
        const float4* t3 = (const float4*)(hsh + (slot * 4 + 3) * HID);
#pragma unroll 4
        for (int k4 = 0; k4 < HID / 4; k4++) {
            float4 s0 = t0[k4], s1 = t1[k4], s2 = t2[k4], s3 = t3[k4];
#pragma unroll
            for (int j = 0; j < 4; j++) {
                ulonglong2 w = ((const ulonglong2*)wsh)[(k4 * 4 + j) * 32 + cg];
                fma2x2(a0, pack2s(((const float*)&s0)[j]), w);
                fma2x2(a1, pack2s(((const float*)&s1)[j]), w);
                fma2x2(a2, pack2s(((const float*)&s2)[j]), w);
                fma2x2(a3, pack2s(((const float*)&s3)[j]), w);
            }
        }

        int node = base + slot * 4;
#pragma unroll
        for (int j = 0; j < 4; j++) {
            int n = node + j;
            if (n < N_NODES) {
                float4 a = acc_to_f4(j == 0 ? a0 : j == 1 ? a1 : j == 2 ? a2 : a3);
                int g = batch[n];
                float* addr = pool + g * OUT_DIM + cg * 4;
                asm volatile("red.global.add.v4.f32 [%0], {%1, %2, %3, %4};"
                             :: "l"(addr), "f"(a.x), "f"(a.y), "f"(a.z), "f"(a.w)
                             : "memory");
                if (cg == 0)
                    atomicAdd(cnt + g, 1.0f);
            }
        }
    }
}

// ---------------------------------------------------------------------------
__global__ void finalize_kernel(const float* __restrict__ pool,
                                const float* __restrict__ cnt,
                                float* __restrict__ out) {
    int i = blockIdx.x * blockDim.x + threadIdx.x;
    if (i < N_GRAPHS * OUT_DIM)
        out[i] = pool[i] / fmaxf(cnt[i >> 7], 1.0f);
}

// ---------------------------------------------------------------------------
extern "C" void kernel_launch(void* const* d_in, const int* in_sizes, int n_in,
                              void* d_out, int out_size) {
    const float* x     = (const float*)d_in[0];
    const int*   ei    = (const int*)d_in[1];   // [2, E] int32
    const int*   batch = (const int*)d_in[2];   // [N] int32
    const float* W_in  = (const float*)d_in[3];
    const float* b_in  = (const float*)d_in[4];
    const float* W1_0  = (const float*)d_in[5];
    const float* b1_0  = (const float*)d_in[6];
    const float* W2_0  = (const float*)d_in[7];
    const float* b2_0  = (const float*)d_in[8];
    const float* W1_1  = (const float*)d_in[9];
    const float* b1_1  = (const float*)d_in[10];
    const float* W2_1  = (const float*)d_in[11];
    const float* b2_1  = (const float*)d_in[12];
    const float* W_out = (const float*)d_in[13];
    const float* b_out = (const float*)d_in[14];
    const int n_edges  = in_sizes[1] / 2;
    float* out = (float*)d_out;

    void* basep = nullptr;
    cudaGetSymbolAddress(&basep, g_scratch);
    float* h0   = (float*)basep;
    float* h1   = h0 + NH;
    float* a0   = h1 + NH;
    float* a1   = a0 + NH;
    float* pool = a1 + NH;
    float* cnt  = pool + N_GRAPHS * OUT_DIM;

    const int zero_n4 = (2 * NH + N_GRAPHS * OUT_DIM + N_GRAPHS) / 4;
    zero_kernel<<<512, 256>>>(a0, zero_n4);

    cudaFuncSetAttribute(proj_in_kernel,
                         cudaFuncAttributeMaxDynamicSharedMemorySize, 65536);
    const int g64 = (N_NODES + 63) / 64;
    const int g32 = (N_NODES + 31) / 32;
    const int ge  = (n_edges * 16 + 255) / 256;

    proj_in_kernel<<<g64, 256, 65536>>>(x, W_in, b_in, h0);
    scatter_kernel<<<ge, 256>>>(ei, h0, a0, n_edges);
    gin_mlp_kernel<<<g64, 256>>>(h0, a0, W1_0, b1_0, W2_0, b2_0, h1);
    scatter_kernel<<<ge, 256>>>(ei, h1, a1, n_edges);
    gin_mlp_kernel<<<g64, 256>>>(h1, a1, W1_1, b1_1, W2_1, b2_1, h0);
    proj_out_pool_kernel<<<g32, 256>>>(h0, batch, W_out, b_out, pool, cnt);
    finalize_kernel<<<(N_GRAPHS * OUT_DIM + 255) / 256, 256>>>(pool, cnt, out);
}